// round 1
// baseline (speedup 1.0000x reference)
#include <cuda_runtime.h>
#include <cuda_bf16.h>

#define Bv 2
#define Cv 36
#define Hv 512
#define Wv 512
#define Kv 9

// Transposed features: [B, H, W, C] so one spatial sample = 144B contiguous.
__device__ float g_featT[(size_t)Bv * Hv * Wv * Cv];

// ---------------------------------------------------------------------------
// Transpose [B,C,H,W] -> [B,H,W,C]. One block per (b, h, 128-wide w chunk).
// ---------------------------------------------------------------------------
__global__ __launch_bounds__(256) void transpose_kernel(const float* __restrict__ feat) {
    __shared__ float tile[Cv][129];  // +1 pad word via 129 stride (odd) -> conflict-free
    int b = blockIdx.z;
    int h = blockIdx.y;
    int w0 = blockIdx.x * 128;

    // Coalesced read over w for each channel row.
    for (int idx = threadIdx.x; idx < Cv * 128; idx += 256) {
        int c = idx >> 7;
        int w = idx & 127;
        tile[c][w] = feat[(((size_t)b * Cv + c) * Hv + h) * Wv + w0 + w];
    }
    __syncthreads();

    // Coalesced write of the 128*36 contiguous output floats.
    float* outp = g_featT + (((size_t)b * Hv + h) * Wv + w0) * Cv;
    for (int e = threadIdx.x; e < 128 * Cv; e += 256) {
        int w = e / Cv;
        int c = e - w * Cv;
        outp[e] = tile[c][w];
    }
}

// ---------------------------------------------------------------------------
// Main evaluation: one thread per output pixel.
// ---------------------------------------------------------------------------
__global__ __launch_bounds__(256) void eval_kernel(
    const float* __restrict__ offx,
    const float* __restrict__ offy,
    float* __restrict__ out)
{
    const int x = blockIdx.x * 32 + threadIdx.x;  // blockDim = (32, 8)
    const int y = blockIdx.y * 8 + threadIdx.y;
    const int b = blockIdx.z;

    // Load this pixel's 36 feature values (contiguous, 9 x float4).
    const float4* Fp = reinterpret_cast<const float4*>(
        g_featT + (((size_t)b * Hv + y) * Wv + x) * Cv);
    float4 F[9];
#pragma unroll
    for (int i = 0; i < 9; i++) F[i] = __ldg(Fp + i);

    // Online softmax state (temperature 1000 folded into t).
    float m = -1e30f, se = 0.f, sx = 0.f, sy = 0.f;

    const size_t obase = (((size_t)b * Kv) * Hv + y) * Wv + x;
    const size_t ostride = (size_t)Hv * Wv;

    for (int k = 0; k < Kv; k++) {
        const float oxk = __ldg(offx + obase + (size_t)k * ostride);
        const float oyk = __ldg(offy + obase + (size_t)k * ostride);

        // Clamped sample coordinates (align_corners=True round-trip == identity).
        float rx = fminf(fmaxf((float)x + oxk, 0.f), (float)(Wv - 1));
        float ry = fminf(fmaxf((float)y + oyk, 0.f), (float)(Hv - 1));
        float fx = floorf(rx), fy = floorf(ry);
        float wx = rx - fx, wy = ry - fy;
        int x0 = (int)fx, y0 = (int)fy;
        int x1 = min(x0 + 1, Wv - 1), y1 = min(y0 + 1, Hv - 1);

        const float4* p00 = reinterpret_cast<const float4*>(
            g_featT + (((size_t)b * Hv + y0) * Wv + x0) * Cv);
        const float4* p01 = reinterpret_cast<const float4*>(
            g_featT + (((size_t)b * Hv + y0) * Wv + x1) * Cv);
        const float4* p10 = reinterpret_cast<const float4*>(
            g_featT + (((size_t)b * Hv + y1) * Wv + x0) * Cv);
        const float4* p11 = reinterpret_cast<const float4*>(
            g_featT + (((size_t)b * Hv + y1) * Wv + x1) * Cv);

        // 9 group-pair L1 sums: s[3*g + gp] = sum_j |F[12g+j] - A[12gp+j]|
        float s[9];
#pragma unroll
        for (int i = 0; i < 9; i++) s[i] = 0.f;

#pragma unroll
        for (int i = 0; i < 9; i++) {
            float4 v00 = __ldg(p00 + i);
            float4 v01 = __ldg(p01 + i);
            float4 v10 = __ldg(p10 + i);
            float4 v11 = __ldg(p11 + i);

            float4 a;
            {
                float t0 = fmaf(wx, v01.x - v00.x, v00.x);
                float t1 = fmaf(wx, v11.x - v10.x, v10.x);
                a.x = fmaf(wy, t1 - t0, t0);
            }
            {
                float t0 = fmaf(wx, v01.y - v00.y, v00.y);
                float t1 = fmaf(wx, v11.y - v10.y, v10.y);
                a.y = fmaf(wy, t1 - t0, t0);
            }
            {
                float t0 = fmaf(wx, v01.z - v00.z, v00.z);
                float t1 = fmaf(wx, v11.z - v10.z, v10.z);
                a.z = fmaf(wy, t1 - t0, t0);
            }
            {
                float t0 = fmaf(wx, v01.w - v00.w, v00.w);
                float t1 = fmaf(wx, v11.w - v10.w, v10.w);
                a.w = fmaf(wy, t1 - t0, t0);
            }

            const int gp = i / 3;          // sampled group (0..2)
            const int r  = i - gp * 3;     // float4 index within group
#pragma unroll
            for (int g = 0; g < 3; g++) {
                float4 f = F[3 * g + r];
                s[3 * g + gp] += fabsf(f.x - a.x) + fabsf(f.y - a.y)
                               + fabsf(f.z - a.z) + fabsf(f.w - a.w);
            }
        }

        float smin = s[0];
#pragma unroll
        for (int i = 1; i < 9; i++) smin = fminf(smin, s[i]);

        // strength * 1000 = -(smin/12) * 1000
        float t = smin * (-1000.f / 12.f);

        // Online softmax update.
        if (t > m) {
            float c = __expf(m - t);
            se *= c; sx *= c; sy *= c;
            m = t;
        }
        float e = __expf(t - m);
        se += e;
        sx = fmaf(e, oxk, sx);
        sy = fmaf(e, oyk, sy);
    }

    float ox = sx / se;
    float oy = sy / se;
    ox = fminf(fmaxf(ox + (float)x, 0.f), (float)(Wv - 1)) - (float)x;
    oy = fminf(fmaxf(oy + (float)y, 0.f), (float)(Hv - 1)) - (float)y;

    const size_t pix = ((size_t)b * Hv + y) * Wv + x;
    out[pix] = ox;
    out[(size_t)Bv * Hv * Wv + pix] = oy;
}

extern "C" void kernel_launch(void* const* d_in, const int* in_sizes, int n_in,
                              void* d_out, int out_size) {
    const float* features = (const float*)d_in[0];
    const float* offset_x = (const float*)d_in[1];
    const float* offset_y = (const float*)d_in[2];
    // d_in[3] = left_x (== w), d_in[4] = left_y (== h): recomputed from indices.
    float* out = (float*)d_out;

    dim3 tgrid(Wv / 128, Hv, Bv);
    transpose_kernel<<<tgrid, 256>>>(features);

    dim3 block(32, 8);
    dim3 grid(Wv / 32, Hv / 8, Bv);
    eval_kernel<<<grid, block>>>(offset_x, offset_y, out);
}

// round 2
// speedup vs baseline: 1.3927x; 1.3927x over previous
#include <cuda_runtime.h>
#include <cuda_bf16.h>

#define Bv 2
#define Cv 36
#define Hv 512
#define Wv 512
#define Kv 9

// Transposed features: [B, H, W, C]; one pixel = 144B contiguous.
__device__ float g_featT[(size_t)Bv * Hv * Wv * Cv];

// ---------------------------------------------------------------------------
// Transpose [B,C,H,W] -> [B,H,W,C].
// ---------------------------------------------------------------------------
__global__ __launch_bounds__(256) void transpose_kernel(const float* __restrict__ feat) {
    __shared__ float tile[Cv][129];
    int b = blockIdx.z;
    int h = blockIdx.y;
    int w0 = blockIdx.x * 128;

    for (int idx = threadIdx.x; idx < Cv * 128; idx += 256) {
        int c = idx >> 7;
        int w = idx & 127;
        tile[c][w] = feat[(((size_t)b * Cv + c) * Hv + h) * Wv + w0 + w];
    }
    __syncthreads();

    float* outp = g_featT + (((size_t)b * Hv + h) * Wv + w0) * Cv;
    for (int e = threadIdx.x; e < 128 * Cv; e += 256) {
        int w = e / Cv;
        int c = e - w * Cv;
        outp[e] = tile[c][w];
    }
}

// ---------------------------------------------------------------------------
// Eval: warp-cooperative gather. Block = 128 threads = 4 warps.
// Each warp owns 32 consecutive-x pixels. Per candidate:
//  load phase : for each pixel p, 18 lanes fetch the 288B row-pair
//               (y-rows yb,yb+1 at columns xb..xb+1, all 36 ch), blend in y,
//               store 72 floats to padded smem.
//  compute    : lane p reads its 72 floats (conflict-free), x-blends, and
//               accumulates the 9 group-pair L1 distances vs its F.
// ---------------------------------------------------------------------------
#define PITCH 76  // words per pixel slot: 72 data + 4 pad (76 mod 32 = 12 -> conflict-free)

__global__ __launch_bounds__(128, 4) void eval_kernel(
    const float* __restrict__ offx,
    const float* __restrict__ offy,
    float* __restrict__ out)
{
    __shared__ float stage[4][32 * PITCH];

    const int tid  = blockIdx.x * 128 + threadIdx.x;
    const int lane = threadIdx.x & 31;
    const int wid  = threadIdx.x >> 5;
    const int x = tid & (Wv - 1);
    const int y = (tid >> 9) & (Hv - 1);
    const int b = tid >> 18;

    float* buf = stage[wid];
    const char* fb = (const char*)g_featT;
    const unsigned laneoff = (unsigned)lane << 4;

    // Per-pixel features: 36 floats contiguous.
    const float4* Fp = reinterpret_cast<const float4*>(
        g_featT + (((size_t)b * Hv + y) * Wv + x) * Cv);
    float4 F[9];
#pragma unroll
    for (int i = 0; i < 9; i++) F[i] = __ldg(Fp + i);

    float m = -1e30f, se = 0.f, sx = 0.f, sy = 0.f;

    const size_t obase = (size_t)b * (Kv * Hv * Wv) + (size_t)y * Wv + x;
    const size_t ostride = (size_t)Hv * Wv;

    for (int k = 0; k < Kv; k++) {
        const float oxk = __ldg(offx + obase + (size_t)k * ostride);
        const float oyk = __ldg(offy + obase + (size_t)k * ostride);

        float rx = fminf(fmaxf((float)x + oxk, 0.f), (float)(Wv - 1));
        float ry = fminf(fmaxf((float)y + oyk, 0.f), (float)(Hv - 1));
        int xb = min((int)floorf(rx), Wv - 2);
        int yb = min((int)floorf(ry), Hv - 2);
        float wx = rx - (float)xb;            // in [0,1]
        float wy = ry - (float)yb;
        // byte offset of (b, yb, xb, 0); row-pair spans 288B, next y-row +W*144B.
        unsigned off = (unsigned)(((b * Hv + yb) * Wv + xb)) * 144u;

        // ---- load phase: one pixel per iteration, 18 lanes active ----
#pragma unroll 8
        for (int p = 0; p < 32; p++) {
            unsigned off_p = __shfl_sync(0xffffffffu, off, p);
            float    wy_p  = __shfl_sync(0xffffffffu, wy,  p);
            if (lane < 18) {
                float4 r0 = *reinterpret_cast<const float4*>(fb + off_p + laneoff);
                float4 r1 = *reinterpret_cast<const float4*>(fb + off_p + laneoff + (unsigned)(Wv * Cv * 4));
                float4 t;
                t.x = fmaf(wy_p, r1.x - r0.x, r0.x);
                t.y = fmaf(wy_p, r1.y - r0.y, r0.y);
                t.z = fmaf(wy_p, r1.z - r0.z, r0.z);
                t.w = fmaf(wy_p, r1.w - r0.w, r0.w);
                *reinterpret_cast<float4*>(buf + p * PITCH + lane * 4) = t;
            }
        }
        __syncwarp();

        // ---- compute phase: lane p handles its own pixel ----
        float s[9];
#pragma unroll
        for (int i = 0; i < 9; i++) s[i] = 0.f;

        const float* mybuf = buf + lane * PITCH;
#pragma unroll
        for (int i = 0; i < 9; i++) {
            float4 lo = *reinterpret_cast<const float4*>(mybuf + 4 * i);        // x = xb, ch 4i..
            float4 hi = *reinterpret_cast<const float4*>(mybuf + 36 + 4 * i);   // x = xb+1
            float4 a;
            a.x = fmaf(wx, hi.x - lo.x, lo.x);
            a.y = fmaf(wx, hi.y - lo.y, lo.y);
            a.z = fmaf(wx, hi.z - lo.z, lo.z);
            a.w = fmaf(wx, hi.w - lo.w, lo.w);

            const int gp = i / 3;        // sampled-channel group
            const int r  = i - gp * 3;   // float4 index within group
#pragma unroll
            for (int g = 0; g < 3; g++) {
                float4 f = F[3 * g + r];
                s[3 * g + gp] += fabsf(f.x - a.x) + fabsf(f.y - a.y)
                               + fabsf(f.z - a.z) + fabsf(f.w - a.w);
            }
        }

        float smin = s[0];
#pragma unroll
        for (int i = 1; i < 9; i++) smin = fminf(smin, s[i]);

        float t = smin * (-1000.f / 12.f);

        if (t > m) {
            float c = __expf(m - t);
            se *= c; sx *= c; sy *= c;
            m = t;
        }
        float e = __expf(t - m);
        se += e;
        sx = fmaf(e, oxk, sx);
        sy = fmaf(e, oyk, sy);

        __syncwarp();  // protect stage buffer before next candidate's load phase
    }

    float ox = sx / se;
    float oy = sy / se;
    ox = fminf(fmaxf(ox + (float)x, 0.f), (float)(Wv - 1)) - (float)x;
    oy = fminf(fmaxf(oy + (float)y, 0.f), (float)(Hv - 1)) - (float)y;

    const size_t pix = ((size_t)b * Hv + y) * Wv + x;
    out[pix] = ox;
    out[(size_t)Bv * Hv * Wv + pix] = oy;
}

extern "C" void kernel_launch(void* const* d_in, const int* in_sizes, int n_in,
                              void* d_out, int out_size) {
    const float* features = (const float*)d_in[0];
    const float* offset_x = (const float*)d_in[1];
    const float* offset_y = (const float*)d_in[2];
    float* out = (float*)d_out;

    dim3 tgrid(Wv / 128, Hv, Bv);
    transpose_kernel<<<tgrid, 256>>>(features);

    int total = Bv * Hv * Wv;
    eval_kernel<<<total / 128, 128>>>(offset_x, offset_y, out);
}